// round 15
// baseline (speedup 1.0000x reference)
#include <cuda_runtime.h>
#include <cuda_fp16.h>
#include <cstdint>

#define JN    24
#define DN    256
#define HN    4
#define DHC   64
#define TPB   256
#define EMAX  80
#define HSTR  260                 // padded fp32 row stride for h staging
#define DYN_SMEM (32 * HSTR * 4)  // 33280 B: A image (16KB) then h fp32 (32 rows)

// W fragment image (fp16): [nt-pair 0..15][k-step 0..15][lane][4 regs]
__device__ uint32_t g_Bfrag[16][16][32][4];   // 128 KB

__device__ __forceinline__ uint32_t smem_u32(const void* p) {
    uint32_t a;
    asm("{ .reg .u64 t; cvta.to.shared.u64 t, %1; cvt.u32.u64 %0, t; }" : "=r"(a) : "l"(p));
    return a;
}
__device__ __forceinline__ uint32_t packh(__half a, __half b) {
    return (uint32_t)__half_as_ushort(a) | ((uint32_t)__half_as_ushort(b) << 16);
}

#define LDMATRIX_X4(r0, r1, r2, r3, addr) \
    asm volatile("ldmatrix.sync.aligned.m8n8.x4.shared.b16 {%0,%1,%2,%3}, [%4];" \
        : "=r"(r0), "=r"(r1), "=r"(r2), "=r"(r3) : "r"(addr))

#define MMA_F16(acc, a, b0, b1) \
    asm volatile("mma.sync.aligned.m16n8k16.row.col.f32.f16.f16.f32 " \
        "{%0,%1,%2,%3}, {%4,%5,%6,%7}, {%8,%9}, {%0,%1,%2,%3};" \
        : "+f"((acc)[0]), "+f"((acc)[1]), "+f"((acc)[2]), "+f"((acc)[3]) \
        : "r"((a)[0]), "r"((a)[1]), "r"((a)[2]), "r"((a)[3]), "r"(b0), "r"(b1))

// ---------------- prep: W -> fp16 fragment-linear image (nt-paired) ----------------
__global__ void prep_W(const float* __restrict__ W) {
    int idx = blockIdx.x * 256 + threadIdx.x;   // 0..8191 = pr*512 + ks*32 + lane
    if (idx >= 8192) return;
    int pr = idx >> 9, ks = (idx >> 5) & 15, l = idx & 31;
#pragma unroll
    for (int r = 0; r < 4; r++) {
        int nt = pr * 2 + (r >> 1);
        int rr = r & 1;
        int k = ks * 16 + rr * 8 + (l & 3) * 2;
        int n = nt * 8 + (l >> 2);
        float v0 = W[(size_t)k * DN + n];
        float v1 = W[(size_t)(k + 1) * DN + n];
        g_Bfrag[pr][ks][l][r] = packh(__float2half(v0), __float2half(v1));
    }
}

// ---------------- main fused kernel: 1 graph per CTA, 2m x 4n warp grid ----------------
__global__ void __launch_bounds__(TPB, 4) gat_mma_kernel(
    const float* __restrict__ x,
    const float* __restrict__ att_src_g, const float* __restrict__ att_dst_g,
    const float* __restrict__ bias, const int* __restrict__ edge_index,
    float* __restrict__ out, int E0)
{
    extern __shared__ unsigned char dynraw[];
    __shared__ float s_att[2 * DN];
    __shared__ float s_bias[DN];
    __shared__ float s_as[JN * HN], s_ad[JN * HN];
    __shared__ float s_sc[EMAX * HN];
    __shared__ int   s_src[EMAX], s_dst[EMAX];
    __shared__ int   s_inc[JN][4], s_cnt[JN];

    const int tid = threadIdx.x;
    const int w = tid >> 5, l = tid & 31;
    const int gid = l >> 2, tig = l & 3;
    const int head = w >> 1, mt = w & 1;    // warp = (m-tile, head)
    const uint32_t dynb = smem_u32(dynraw);
    const int E = E0 + JN;

    // ---- small tensors ----
    for (int i = tid; i < 2 * DN; i += TPB)
        s_att[i] = (i < DN) ? att_src_g[i] : att_dst_g[i - DN];
    for (int i = tid; i < DN; i += TPB) s_bias[i] = bias[i];
    if (tid < E0) { s_src[tid] = edge_index[tid]; s_dst[tid] = edge_index[E0 + tid]; }
    if (tid < JN) { s_src[E0 + tid] = tid; s_dst[E0 + tid] = tid; }

    // ---- convert x -> fp16 A image in SMEM (XOR-swizzled), rows 24..31 zero ----
    {
        const float* xg = x + (size_t)blockIdx.x * (JN * DN);
        for (int i = tid; i < 256; i += TPB)
            *(uint4*)(dynraw + 24 * 512 + i * 16) = make_uint4(0, 0, 0, 0);
#pragma unroll
        for (int i = 0; i < 3; i++) {
            int task = tid + i * TPB;          // 0..767 : row (0..23), 8-float chunk
            int r = task >> 5, c = task & 31;
            const float4 a = *(const float4*)(xg + (size_t)r * DN + c * 8);
            const float4 b = *(const float4*)(xg + (size_t)r * DN + c * 8 + 4);
            uint32_t hi[4];
            hi[0] = packh(__float2half(a.x), __float2half(a.y));
            hi[1] = packh(__float2half(a.z), __float2half(a.w));
            hi[2] = packh(__float2half(b.x), __float2half(b.y));
            hi[3] = packh(__float2half(b.z), __float2half(b.w));
            uint32_t off = (uint32_t)r * 512u + (uint32_t)((c ^ (r & 7)) << 4);
            *(uint4*)(dynraw + off) = make_uint4(hi[0], hi[1], hi[2], hi[3]);
        }
    }

    // incoming-edge lists (chain graph: cnt <= 3)
    if (tid < JN) {
        int c = 0;
        for (int e = 0; e < E; e++)
            if (s_dst[e] == tid) { if (c < 4) s_inc[tid][c] = e; c++; }
        s_cnt[tid] = c < 4 ? c : 4;
    }
    __syncthreads();

    // ---- GEMM: warp owns 16 rows (m-tile mt) x 64 cols (head) ----
    float acc[8][4];
#pragma unroll
    for (int nt = 0; nt < 8; nt++)
        acc[nt][0] = acc[nt][1] = acc[nt][2] = acc[nt][3] = 0.f;

    const uint4* bp = (const uint4*)&g_Bfrag[head * 4][0][l][0];
    const uint32_t arow = (uint32_t)(l & 15);
    const uint32_t abase = dynb + ((uint32_t)(mt * 16) + arow) * 512u;

#pragma unroll 4
    for (int ks = 0; ks < 16; ks++) {
        // issue all independent B loads first (MLP=4), overlap with ldmatrix
        const uint4 b0 = __ldg(bp + 0 * 512 + ks * 32);
        const uint4 b1 = __ldg(bp + 1 * 512 + ks * 32);
        const uint4 b2 = __ldg(bp + 2 * 512 + ks * 32);
        const uint4 b3 = __ldg(bp + 3 * 512 + ks * 32);
        const uint32_t kc = (uint32_t)(ks * 2 + (l >> 4));
        const uint32_t koff = (kc ^ (arow & 7u)) << 4;
        uint32_t ah[4];
        LDMATRIX_X4(ah[0], ah[1], ah[2], ah[3], abase + koff);
        MMA_F16(acc[0], ah, b0.x, b0.y); MMA_F16(acc[1], ah, b0.z, b0.w);
        MMA_F16(acc[2], ah, b1.x, b1.y); MMA_F16(acc[3], ah, b1.z, b1.w);
        MMA_F16(acc[4], ah, b2.x, b2.y); MMA_F16(acc[5], ah, b2.z, b2.w);
        MMA_F16(acc[6], ah, b3.x, b3.y); MMA_F16(acc[7], ah, b3.z, b3.w);
    }
    __syncthreads();   // all warps done reading A image before h overwrite

    // ---- store h fp32 to SMEM (incl. pad rows; stride HSTR) ----
    float* hb = (float*)dynraw;
    {
#pragma unroll
        for (int nt = 0; nt < 8; nt++) {
            const int col = head * DHC + nt * 8 + 2 * tig;
            *(float2*)&hb[(mt * 16 + gid) * HSTR + col] =
                make_float2(acc[nt][0], acc[nt][1]);
            *(float2*)&hb[(mt * 16 + gid + 8) * HSTR + col] =
                make_float2(acc[nt][2], acc[nt][3]);
        }
    }

    // ---- attention dots from accumulators: warp-local butterfly, plain stores ----
    {
        float sa0 = 0.f, sd0 = 0.f, sa1 = 0.f, sd1 = 0.f;
#pragma unroll
        for (int nt = 0; nt < 8; nt++) {
            const float2 av = *(const float2*)&s_att[head * DHC + nt * 8 + 2 * tig];
            const float2 bv = *(const float2*)&s_att[DN + head * DHC + nt * 8 + 2 * tig];
            sa0 += acc[nt][0] * av.x + acc[nt][1] * av.y;
            sd0 += acc[nt][0] * bv.x + acc[nt][1] * bv.y;
            sa1 += acc[nt][2] * av.x + acc[nt][3] * av.y;
            sd1 += acc[nt][2] * bv.x + acc[nt][3] * bv.y;
        }
        sa0 += __shfl_xor_sync(0xffffffffu, sa0, 1); sa0 += __shfl_xor_sync(0xffffffffu, sa0, 2);
        sd0 += __shfl_xor_sync(0xffffffffu, sd0, 1); sd0 += __shfl_xor_sync(0xffffffffu, sd0, 2);
        sa1 += __shfl_xor_sync(0xffffffffu, sa1, 1); sa1 += __shfl_xor_sync(0xffffffffu, sa1, 2);
        sd1 += __shfl_xor_sync(0xffffffffu, sd1, 1); sd1 += __shfl_xor_sync(0xffffffffu, sd1, 2);
        if (tig == 0) {
            const int r0 = mt * 16 + gid;          // always < 24
            const int r1 = r0 + 8;                 // pad when mt==1
            s_as[r0 * HN + head] = sa0; s_ad[r0 * HN + head] = sd0;
            if (r1 < JN) { s_as[r1 * HN + head] = sa1; s_ad[r1 * HN + head] = sd1; }
        }
    }
    __syncthreads();

    // ---- merged scores + segment softmax -> alpha in s_sc ----
    if (tid < JN * HN) {
        const int j = tid >> 2, hh = tid & 3;
        const int cnt = s_cnt[j];
        const float adj = s_ad[j * HN + hh];
        float sc[4], m = -3.402823466e38f;
        for (int t = 0; t < cnt; t++) {
            const int e = s_inc[j][t];
            float v = s_as[s_src[e] * HN + hh] + adj;
            v = (v >= 0.f) ? v : 0.2f * v;
            sc[t] = v;
            m = fmaxf(m, v);
        }
        float den = 0.f;
        for (int t = 0; t < cnt; t++) { sc[t] = __expf(sc[t] - m); den += sc[t]; }
        const float inv = 1.f / den;
        for (int t = 0; t < cnt; t++) s_sc[s_inc[j][t] * HN + hh] = sc[t] * inv;
    }
    __syncthreads();

    // ---- weighted gather + bias -> out ----
    float* og = out + (size_t)blockIdx.x * (JN * DN);
    for (int idx = tid; idx < JN * 64; idx += TPB) {
        const int j = idx >> 6, q = idx & 63;       // q: float4 column group
        const int hh = q >> 4;
        float4 o = ((const float4*)s_bias)[q];
        const int cnt = s_cnt[j];
        for (int t = 0; t < cnt; t++) {
            const int e = s_inc[j][t];
            const float a = s_sc[e * HN + hh];
            const float4 hv = *(const float4*)&hb[s_src[e] * HSTR + q * 4];
            o.x += a * hv.x; o.y += a * hv.y; o.z += a * hv.z; o.w += a * hv.w;
        }
        *(float4*)&og[(size_t)j * DN + q * 4] = o;
    }
}

extern "C" void kernel_launch(void* const* d_in, const int* in_sizes, int n_in,
                              void* d_out, int out_size) {
    const float* x        = (const float*)d_in[0];
    const float* W        = (const float*)d_in[1];
    const float* att_src  = (const float*)d_in[2];
    const float* att_dst  = (const float*)d_in[3];
    const float* bias     = (const float*)d_in[4];
    const int*   edge_idx = (const int*)d_in[5];
    float* out = (float*)d_out;

    const int E0   = in_sizes[5] / 2;            // 46
    const int grid = in_sizes[0] / (JN * DN);    // 4096

    cudaFuncSetAttribute(gat_mma_kernel, cudaFuncAttributeMaxDynamicSharedMemorySize, DYN_SMEM);
    prep_W<<<32, 256>>>(W);
    gat_mma_kernel<<<grid, TPB, DYN_SMEM>>>(x, att_src, att_dst, bias, edge_idx, out, E0);
}

// round 17
// speedup vs baseline: 1.5955x; 1.5955x over previous
#include <cuda_runtime.h>
#include <cuda_fp16.h>
#include <cstdint>

#define JN    24
#define DN    256
#define HN    4
#define DHC   64
#define TPB   256
#define EMAX  80
#define HSTR  260                 // padded fp32 row stride for h staging
#define DYN_SMEM (32 * HSTR * 4)  // 33280 B: A image (16KB) then h fp32 (32 rows)

// W fragment image (fp16): [nt-pair 0..15][k-step 0..15][lane][4 regs]
__device__ uint32_t g_Bfrag[16][16][32][4];   // 128 KB

__device__ __forceinline__ uint32_t smem_u32(const void* p) {
    uint32_t a;
    asm("{ .reg .u64 t; cvta.to.shared.u64 t, %1; cvt.u32.u64 %0, t; }" : "=r"(a) : "l"(p));
    return a;
}
__device__ __forceinline__ uint32_t packh(__half a, __half b) {
    return (uint32_t)__half_as_ushort(a) | ((uint32_t)__half_as_ushort(b) << 16);
}

#define LDMATRIX_X4(r0, r1, r2, r3, addr) \
    asm volatile("ldmatrix.sync.aligned.m8n8.x4.shared.b16 {%0,%1,%2,%3}, [%4];" \
        : "=r"(r0), "=r"(r1), "=r"(r2), "=r"(r3) : "r"(addr))

#define MMA_F16(acc, a, b0, b1) \
    asm volatile("mma.sync.aligned.m16n8k16.row.col.f32.f16.f16.f32 " \
        "{%0,%1,%2,%3}, {%4,%5,%6,%7}, {%8,%9}, {%0,%1,%2,%3};" \
        : "+f"((acc)[0]), "+f"((acc)[1]), "+f"((acc)[2]), "+f"((acc)[3]) \
        : "r"((a)[0]), "r"((a)[1]), "r"((a)[2]), "r"((a)[3]), "r"(b0), "r"(b1))

// ---------------- prep: W -> fp16 fragment-linear image (nt-paired) ----------------
__global__ void prep_W(const float* __restrict__ W) {
    int idx = blockIdx.x * 256 + threadIdx.x;   // 0..8191 = pr*512 + ks*32 + lane
    if (idx >= 8192) return;
    int pr = idx >> 9, ks = (idx >> 5) & 15, l = idx & 31;
#pragma unroll
    for (int r = 0; r < 4; r++) {
        int nt = pr * 2 + (r >> 1);
        int rr = r & 1;
        int k = ks * 16 + rr * 8 + (l & 3) * 2;
        int n = nt * 8 + (l >> 2);
        float v0 = W[(size_t)k * DN + n];
        float v1 = W[(size_t)(k + 1) * DN + n];
        g_Bfrag[pr][ks][l][r] = packh(__float2half(v0), __float2half(v1));
    }
}

// ---------------- main fused kernel: 1 graph per CTA, 2m x 4n warp grid ----------------
__global__ void __launch_bounds__(TPB, 4) gat_mma_kernel(
    const float* __restrict__ x,
    const float* __restrict__ att_src_g, const float* __restrict__ att_dst_g,
    const float* __restrict__ bias, const int* __restrict__ edge_index,
    float* __restrict__ out, int E0)
{
    extern __shared__ unsigned char dynraw[];
    __shared__ float s_att[2 * DN];
    __shared__ float s_bias[DN];
    __shared__ float s_as[JN * HN], s_ad[JN * HN];
    __shared__ float s_sc[EMAX * HN];
    __shared__ int   s_src[EMAX], s_dst[EMAX];
    __shared__ int   s_inc[JN][4], s_cnt[JN];

    const int tid = threadIdx.x;
    const int w = tid >> 5, l = tid & 31;
    const int gid = l >> 2, tig = l & 3;
    const int head = w >> 1, mt = w & 1;    // warp = (m-tile, head)
    const uint32_t dynb = smem_u32(dynraw);
    const int E = E0 + JN;

    // ---- small tensors ----
    for (int i = tid; i < 2 * DN; i += TPB)
        s_att[i] = (i < DN) ? att_src_g[i] : att_dst_g[i - DN];
    for (int i = tid; i < DN; i += TPB) s_bias[i] = bias[i];
    if (tid < E0) { s_src[tid] = edge_index[tid]; s_dst[tid] = edge_index[E0 + tid]; }
    if (tid < JN) { s_src[E0 + tid] = tid; s_dst[E0 + tid] = tid; }

    // ---- convert x -> fp16 A image in SMEM (XOR-swizzled), rows 24..31 zero ----
    {
        const float* xg = x + (size_t)blockIdx.x * (JN * DN);
        for (int i = tid; i < 256; i += TPB)
            *(uint4*)(dynraw + 24 * 512 + i * 16) = make_uint4(0, 0, 0, 0);
#pragma unroll
        for (int i = 0; i < 3; i++) {
            int task = tid + i * TPB;          // 0..767 : row (0..23), 8-float chunk
            int r = task >> 5, c = task & 31;
            const float4 a = *(const float4*)(xg + (size_t)r * DN + c * 8);
            const float4 b = *(const float4*)(xg + (size_t)r * DN + c * 8 + 4);
            uint32_t hi[4];
            hi[0] = packh(__float2half(a.x), __float2half(a.y));
            hi[1] = packh(__float2half(a.z), __float2half(a.w));
            hi[2] = packh(__float2half(b.x), __float2half(b.y));
            hi[3] = packh(__float2half(b.z), __float2half(b.w));
            uint32_t off = (uint32_t)r * 512u + (uint32_t)((c ^ (r & 7)) << 4);
            *(uint4*)(dynraw + off) = make_uint4(hi[0], hi[1], hi[2], hi[3]);
        }
    }
    __syncthreads();   // s_src/s_dst + A image fully visible

    // incoming-edge lists (chain graph: cnt <= 3) — AFTER barrier (race fix)
    // readers (softmax/gather) are behind the GEMM-end barrier below
    if (tid < JN) {
        int c = 0;
        for (int e = 0; e < E; e++)
            if (s_dst[e] == tid) { if (c < 4) s_inc[tid][c] = e; c++; }
        s_cnt[tid] = c < 4 ? c : 4;
    }

    // ---- GEMM: warp owns 16 rows (m-tile mt) x 64 cols (head) ----
    float acc[8][4];
#pragma unroll
    for (int nt = 0; nt < 8; nt++)
        acc[nt][0] = acc[nt][1] = acc[nt][2] = acc[nt][3] = 0.f;

    const uint4* bp = (const uint4*)&g_Bfrag[head * 4][0][l][0];
    const uint32_t arow = (uint32_t)(l & 15);
    const uint32_t abase = dynb + ((uint32_t)(mt * 16) + arow) * 512u;

#pragma unroll 4
    for (int ks = 0; ks < 16; ks++) {
        const uint32_t kc = (uint32_t)(ks * 2 + (l >> 4));
        const uint32_t koff = (kc ^ (arow & 7u)) << 4;
        uint32_t ah[4];
        LDMATRIX_X4(ah[0], ah[1], ah[2], ah[3], abase + koff);
        const uint4 b0 = __ldg(bp + 0 * 512 + ks * 32);
        const uint4 b1 = __ldg(bp + 1 * 512 + ks * 32);
        MMA_F16(acc[0], ah, b0.x, b0.y); MMA_F16(acc[1], ah, b0.z, b0.w);
        MMA_F16(acc[2], ah, b1.x, b1.y); MMA_F16(acc[3], ah, b1.z, b1.w);
        const uint4 b2 = __ldg(bp + 2 * 512 + ks * 32);
        const uint4 b3 = __ldg(bp + 3 * 512 + ks * 32);
        MMA_F16(acc[4], ah, b2.x, b2.y); MMA_F16(acc[5], ah, b2.z, b2.w);
        MMA_F16(acc[6], ah, b3.x, b3.y); MMA_F16(acc[7], ah, b3.z, b3.w);
    }
    __syncthreads();   // all warps done reading A image; s_inc/s_cnt visible

    // ---- store h fp32 to SMEM (incl. pad rows; stride HSTR) ----
    float* hb = (float*)dynraw;
    {
#pragma unroll
        for (int nt = 0; nt < 8; nt++) {
            const int col = head * DHC + nt * 8 + 2 * tig;
            *(float2*)&hb[(mt * 16 + gid) * HSTR + col] =
                make_float2(acc[nt][0], acc[nt][1]);
            *(float2*)&hb[(mt * 16 + gid + 8) * HSTR + col] =
                make_float2(acc[nt][2], acc[nt][3]);
        }
    }

    // ---- attention dots from accumulators: warp-local butterfly, plain stores ----
    {
        float sa0 = 0.f, sd0 = 0.f, sa1 = 0.f, sd1 = 0.f;
#pragma unroll
        for (int nt = 0; nt < 8; nt++) {
            const float2 av = *(const float2*)&s_att[head * DHC + nt * 8 + 2 * tig];
            const float2 bv = *(const float2*)&s_att[DN + head * DHC + nt * 8 + 2 * tig];
            sa0 += acc[nt][0] * av.x + acc[nt][1] * av.y;
            sd0 += acc[nt][0] * bv.x + acc[nt][1] * bv.y;
            sa1 += acc[nt][2] * av.x + acc[nt][3] * av.y;
            sd1 += acc[nt][2] * bv.x + acc[nt][3] * bv.y;
        }
        sa0 += __shfl_xor_sync(0xffffffffu, sa0, 1); sa0 += __shfl_xor_sync(0xffffffffu, sa0, 2);
        sd0 += __shfl_xor_sync(0xffffffffu, sd0, 1); sd0 += __shfl_xor_sync(0xffffffffu, sd0, 2);
        sa1 += __shfl_xor_sync(0xffffffffu, sa1, 1); sa1 += __shfl_xor_sync(0xffffffffu, sa1, 2);
        sd1 += __shfl_xor_sync(0xffffffffu, sd1, 1); sd1 += __shfl_xor_sync(0xffffffffu, sd1, 2);
        if (tig == 0) {
            const int r0 = mt * 16 + gid;          // always < 24
            const int r1 = r0 + 8;                 // pad when mt==1
            s_as[r0 * HN + head] = sa0; s_ad[r0 * HN + head] = sd0;
            if (r1 < JN) { s_as[r1 * HN + head] = sa1; s_ad[r1 * HN + head] = sd1; }
        }
    }
    __syncthreads();

    // ---- merged scores + segment softmax -> alpha in s_sc ----
    if (tid < JN * HN) {
        const int j = tid >> 2, hh = tid & 3;
        const int cnt = s_cnt[j];
        const float adj = s_ad[j * HN + hh];
        float sc[4], m = -3.402823466e38f;
        for (int t = 0; t < cnt; t++) {
            const int e = s_inc[j][t];
            float v = s_as[s_src[e] * HN + hh] + adj;
            v = (v >= 0.f) ? v : 0.2f * v;
            sc[t] = v;
            m = fmaxf(m, v);
        }
        float den = 0.f;
        for (int t = 0; t < cnt; t++) { sc[t] = __expf(sc[t] - m); den += sc[t]; }
        const float inv = 1.f / den;
        for (int t = 0; t < cnt; t++) s_sc[s_inc[j][t] * HN + hh] = sc[t] * inv;
    }
    __syncthreads();

    // ---- weighted gather + bias -> out ----
    float* og = out + (size_t)blockIdx.x * (JN * DN);
    for (int idx = tid; idx < JN * 64; idx += TPB) {
        const int j = idx >> 6, q = idx & 63;       // q: float4 column group
        const int hh = q >> 4;
        float4 o = ((const float4*)s_bias)[q];
        const int cnt = s_cnt[j];
        for (int t = 0; t < cnt; t++) {
            const int e = s_inc[j][t];
            const float a = s_sc[e * HN + hh];
            const float4 hv = *(const float4*)&hb[s_src[e] * HSTR + q * 4];
            o.x += a * hv.x; o.y += a * hv.y; o.z += a * hv.z; o.w += a * hv.w;
        }
        *(float4*)&og[(size_t)j * DN + q * 4] = o;
    }
}

extern "C" void kernel_launch(void* const* d_in, const int* in_sizes, int n_in,
                              void* d_out, int out_size) {
    const float* x        = (const float*)d_in[0];
    const float* W        = (const float*)d_in[1];
    const float* att_src  = (const float*)d_in[2];
    const float* att_dst  = (const float*)d_in[3];
    const float* bias     = (const float*)d_in[4];
    const int*   edge_idx = (const int*)d_in[5];
    float* out = (float*)d_out;

    const int E0   = in_sizes[5] / 2;            // 46
    const int grid = in_sizes[0] / (JN * DN);    // 4096

    cudaFuncSetAttribute(gat_mma_kernel, cudaFuncAttributeMaxDynamicSharedMemorySize, DYN_SMEM);
    prep_W<<<32, 256>>>(W);
    gat_mma_kernel<<<grid, TPB, DYN_SMEM>>>(x, att_src, att_dst, bias, edge_idx, out, E0);
}